// round 17
// baseline (speedup 1.0000x reference)
#include <cuda_runtime.h>
#include <cuda_bf16.h>
#include <cuda_fp16.h>
#include <math.h>
#include <cstdint>

#define BATCH 32
#define CCH   3
#define HH    224
#define NTOK  196
#define PD    768
#define DIM   512
#define NCLS  1000
#define NP    224
#define NPS   (NP*NP)
#define KP    256
#define SLK_M (64*NP)
#define SLK_QV (64*DIM)
#define SLK_H 8192
#define ITERS 50
#define LNEPS 1e-5f

typedef unsigned long long u64;
typedef unsigned int u32;

// ---------------- scratch ----------------
__device__ float g_Q[BATCH*NP*DIM + SLK_QV];
__device__ float g_V[BATCH*NP*DIM + SLK_QV];
__device__ float g_A[BATCH*NPS + SLK_M];
__device__ float g_P[BATCH*NPS + SLK_M];
__device__ float g_Z[BATCH*NPS + SLK_M];
__device__ __align__(16) __half g_xh[BATCH*NTOK*PD];
__device__ __align__(16) __half g_xl[BATCH*NTOK*PD];
__device__ __align__(16) __half g_WhT[2*DIM*PD];
__device__ __align__(16) __half g_WlT[2*DIM*PD];
__device__ __align__(16) __half g_Qh[BATCH*NP*DIM + SLK_QV];
__device__ __align__(16) __half g_Ql[BATCH*NP*DIM + SLK_QV];
__device__ __align__(16) __half g_Vh[BATCH*NP*DIM + SLK_QV];
__device__ __align__(16) __half g_Vl[BATCH*NP*DIM + SLK_QV];
__device__ __align__(16) __half g_Q1h[BATCH*NP*KP + SLK_H];
__device__ __align__(16) __half g_Sh [BATCH*NP*KP + SLK_H];
__device__ __align__(16) __half g_Mh [BATCH*NP*KP + SLK_H];
__device__ __align__(16) __half g_ME [BATCH*NP*KP + SLK_H];

// ---------------- helpers ----------------
__device__ __forceinline__ u32 smem_u32(const void* p) {
    u32 a; asm("{ .reg .u64 t; cvta.to.shared.u64 t, %1; cvt.u32.u64 %0, t; }" : "=r"(a) : "l"(p));
    return a;
}
__device__ __forceinline__ void cp16(u32 dst, const void* src) {
    asm volatile("cp.async.ca.shared.global [%0], [%1], 16;" :: "r"(dst), "l"(src));
}
__device__ __forceinline__ void block_reduce2(float& s, float& s2) {
    __shared__ float sh[2][32];
    int tid = threadIdx.x;
#pragma unroll
    for (int o = 16; o; o >>= 1) {
        s  += __shfl_xor_sync(0xffffffffu, s, o);
        s2 += __shfl_xor_sync(0xffffffffu, s2, o);
    }
    __syncthreads();
    if ((tid & 31) == 0) { sh[0][tid >> 5] = s; sh[1][tid >> 5] = s2; }
    __syncthreads();
    int nw = blockDim.x >> 5;
    float a = 0.f, b = 0.f;
    for (int i = 0; i < nw; i++) { a += sh[0][i]; b += sh[1][i]; }
    s = a; s2 = b;
}
__device__ __forceinline__ void mma16816h(float* d, const u32* a, const u32* b) {
    asm volatile("mma.sync.aligned.m16n8k16.row.col.f32.f16.f16.f32 "
        "{%0,%1,%2,%3}, {%4,%5,%6,%7}, {%8,%9}, {%0,%1,%2,%3};"
        : "+f"(d[0]), "+f"(d[1]), "+f"(d[2]), "+f"(d[3])
        : "r"(a[0]), "r"(a[1]), "r"(a[2]), "r"(a[3]), "r"(b[0]), "r"(b[1]));
}
__device__ __forceinline__ void ldsm4(u32* r, u32 a) {
    asm volatile("ldmatrix.sync.aligned.m8n8.x4.shared.b16 {%0,%1,%2,%3}, [%4];"
        : "=r"(r[0]), "=r"(r[1]), "=r"(r[2]), "=r"(r[3]) : "r"(a));
}
__device__ __forceinline__ void ldsm2(u32* r, u32 a) {
    asm volatile("ldmatrix.sync.aligned.m8n8.x2.shared.b16 {%0,%1}, [%2];"
        : "=r"(r[0]), "=r"(r[1]) : "r"(a));
}
__device__ __forceinline__ u64 split4h(float4 v, u64& lo) {
    __half2 h01 = __floats2half2_rn(v.x, v.y);
    __half2 h23 = __floats2half2_rn(v.z, v.w);
    __half2 l01 = __floats2half2_rn(v.x - __half2float(h01.x), v.y - __half2float(h01.y));
    __half2 l23 = __floats2half2_rn(v.z - __half2float(h23.x), v.w - __half2float(h23.y));
    lo = ((u64)*(u32*)&l23 << 32) | *(u32*)&l01;
    return ((u64)*(u32*)&h23 << 32) | *(u32*)&h01;
}

#define ASTR 232
#define ESTR 232
#define EOFF2 (64*ASTR)                 // poly: sB offset
#define POLY_SMEM ((EOFF2 + 224*ESTR)*2)
#define AD_EOFF (128*ASTR)              // ADMM: sE offset (two A buffers)
#define ADMM_SMEM ((AD_EOFF + 224*ESTR)*2)   // 163328 B
#define EPAIR (16*ESTR*2)

// ldmatrix A address: row-major tile, stride S halfs, warp row base rb
#define LDSM_A_ADDR(base, rb, S, lane) \
    ((base) + (((rb) + ((lane) & 15)) * (S) + (((lane) & 16) ? 8 : 0)) * 2)
// ldmatrix B address: [n][k] tile, stride S halfs, warp col base nb
#define LDSM_B_ADDR(base, nb, S, lane) \
    ((base) + (((nb) + ((lane) & 7) + (((lane) & 16) ? 8 : 0)) * (S) + (((lane) & 8) ? 8 : 0)) * 2)

// shared 13-chunk MMA loop (ADMM / poly), ldmatrix edition
template<int NTM>
__device__ __forceinline__ void mma_loop13(float (&acc)[7][4], u32 aA, u32 bA)
{
#pragma unroll
    for (int kc = 0; kc < 13; kc++) {
        u32 ah[4];
        ldsm4(ah, aA + kc * 32);
#pragma unroll
        for (int pp = 0; pp < NTM / 2; pp++) {
            u32 bf[4];
            ldsm4(bf, bA + pp * EPAIR + kc * 32);
            mma16816h(acc[2 * pp], ah, bf);
            mma16816h(acc[2 * pp + 1], ah, bf + 2);
        }
        if (NTM & 1) {
            u32 bf[2];
            ldsm2(bf, bA + 3 * EPAIR + kc * 32);
            mma16816h(acc[6], ah, bf);
        }
    }
}

// ---------------- 1: patchify+LN(768)+pos AND W transpose+split, one launch ----------------
__global__ void k_patch_wsplit(const float* __restrict__ img,
                               const float* __restrict__ lg,
                               const float* __restrict__ lb,
                               const float* __restrict__ pos,
                               const float* __restrict__ wq,
                               const float* __restrict__ wv) {
    int tid = threadIdx.x;
    if (blockIdx.x < BATCH * NTOK) {
        int blk = blockIdx.x;
        int b = blk / NTOK, n = blk % NTOK;
        int hh = n / 14, ww = n % 14;
        float v[3];
        float s = 0.f, s2 = 0.f;
#pragma unroll
        for (int t = 0; t < 3; t++) {
            int d = tid + t * 256;
            int c = d >> 8, r = d & 255, ph = r >> 4, pw = r & 15;
            float x = img[((b * CCH + c) * HH + hh * 16 + ph) * HH + ww * 16 + pw];
            v[t] = x; s += x; s2 += x * x;
        }
        block_reduce2(s, s2);
        float mu = s * (1.f / 768.f);
        float var = s2 * (1.f / 768.f) - mu * mu;
        float rs = rsqrtf(var + LNEPS);
        size_t base = (size_t)(b * NTOK + n) * PD;
#pragma unroll
        for (int t = 0; t < 3; t++) {
            int d = tid + t * 256;
            float x = (v[t] - mu) * rs * lg[d] + lb[d] + pos[n * PD + d];
            __half h = __float2half(x);
            g_xh[base + d] = h;
            g_xl[base + d] = __float2half(x - __half2float(h));
        }
    } else {
        __shared__ float t[32][33];
        int b2 = blockIdx.x - BATCH * NTOK;      // 0..767 = (24 kx, 16 ny, 2 z)
        int zz = b2 / 384;
        int r2 = b2 - zz * 384;
        int kx = r2 % 24, ny = r2 / 24;
        const float* W = zz ? wv : wq;
        __half* oh = g_WhT + (size_t)zz * DIM * PD;
        __half* ol = g_WlT + (size_t)zz * DIM * PD;
        int k0 = kx * 32, n0 = ny * 32;
        int r = tid >> 3, c4 = (tid & 7) * 4;
        float4 vv = *(const float4*)&W[(k0 + r) * DIM + n0 + c4];
        t[r][c4] = vv.x; t[r][c4 + 1] = vv.y; t[r][c4 + 2] = vv.z; t[r][c4 + 3] = vv.w;
        __syncthreads();
#pragma unroll
        for (int j = 0; j < 4; j++) {
            float x = t[c4 + j][r];
            __half h = __float2half(x);
            oh[(size_t)(n0 + r) * PD + k0 + c4 + j] = h;
            ol[(size_t)(n0 + r) * PD + k0 + c4 + j] = __float2half(x - __half2float(h));
        }
    }
}

// ---------------- 2: projection GEMM, 128x128 tile, ldmatrix ----------------
#define PASTR 72
#define PMT (16*PASTR*2)
#define PJ_AL (128*PASTR)
#define PJ_BH (2*128*PASTR)
#define PJ_BL (3*128*PASTR)
#define PJ_SMEM (4*128*PASTR*2)   // 73728 B

__global__ __launch_bounds__(256, 2) void k_proj_mma(
    const float* __restrict__ wq_b, const float* __restrict__ wv_b)
{
    extern __shared__ __half sp[];
    u32 sb = smem_u32(sp);

    int zz = blockIdx.z;
    const float* bias = zz ? wv_b : wq_b;
    float* out = zz ? g_V : g_Q;
    const __half* WhT = g_WhT + (size_t)zz * DIM * PD;
    const __half* WlT = g_WlT + (size_t)zz * DIM * PD;

    int m0 = blockIdx.x * 128, n0 = blockIdx.y * 128;
    int tid = threadIdx.x;
    int lane = tid & 31, wid = tid >> 5;
    int wm = wid & 3, wn = wid >> 2;
    int grp = lane >> 2, qid = lane & 3;

    u32 aH = LDSM_A_ADDR(sb, wm * 32, PASTR, lane);
    u32 aL = aH + 2 * PJ_AL;
    u32 bH = LDSM_B_ADDR(sb + 2 * PJ_BH, wn * 64, PASTR, lane);
    u32 bL = bH + 2 * (PJ_BL - PJ_BH);

    float acc[2][8][4];
#pragma unroll
    for (int mt = 0; mt < 2; mt++)
#pragma unroll
        for (int nt = 0; nt < 8; nt++)
#pragma unroll
            for (int j = 0; j < 4; j++) acc[mt][nt][j] = 0.f;

    for (int kc = 0; kc < 12; kc++) {
        int k0 = kc * 64;
        for (int i = tid; i < 1024; i += 256) {
            int r = i >> 3, q = i & 7;
            size_t goA = (size_t)(m0 + r) * PD + k0 + q * 8;
            size_t goB = (size_t)(n0 + r) * PD + k0 + q * 8;
            u32 so = 2 * (r * PASTR + q * 8);
            cp16(sb + so, &g_xh[goA]);
            cp16(sb + 2 * PJ_AL + so, &g_xl[goA]);
            cp16(sb + 2 * PJ_BH + so, &WhT[goB]);
            cp16(sb + 2 * PJ_BL + so, &WlT[goB]);
        }
        asm volatile("cp.async.commit_group;" ::: "memory");
        asm volatile("cp.async.wait_group 0;" ::: "memory");
        __syncthreads();
#pragma unroll
        for (int ks = 0; ks < 4; ks++) {
            u32 ah[2][4], al[2][4];
            ldsm4(ah[0], aH + ks * 32);
            ldsm4(ah[1], aH + PMT + ks * 32);
            ldsm4(al[0], aL + ks * 32);
            ldsm4(al[1], aL + PMT + ks * 32);
#pragma unroll
            for (int pp = 0; pp < 4; pp++) {
                u32 bh4[4], bl4[4];
                ldsm4(bh4, bH + pp * PMT + ks * 32);
                ldsm4(bl4, bL + pp * PMT + ks * 32);
#pragma unroll
                for (int mt = 0; mt < 2; mt++) {
                    mma16816h(acc[mt][2 * pp], ah[mt], bh4);
                    mma16816h(acc[mt][2 * pp], al[mt], bh4);
                    mma16816h(acc[mt][2 * pp], ah[mt], bl4);
                    mma16816h(acc[mt][2 * pp + 1], ah[mt], bh4 + 2);
                    mma16816h(acc[mt][2 * pp + 1], al[mt], bh4 + 2);
                    mma16816h(acc[mt][2 * pp + 1], ah[mt], bl4 + 2);
                }
            }
        }
        __syncthreads();
    }
#pragma unroll
    for (int mt = 0; mt < 2; mt++)
#pragma unroll
        for (int rr = 0; rr < 2; rr++) {
            int gm = m0 + wm * 32 + mt * 16 + grp + rr * 8;
            int bb = gm / NTOK, nn = gm - bb * NTOK;
            float* orow = out + ((size_t)bb * NP + nn) * DIM;
#pragma unroll
            for (int nt = 0; nt < 8; nt++) {
                int gc = n0 + wn * 64 + nt * 8 + qid * 2;
                float2 o;
                o.x = acc[mt][nt][rr * 2 + 0] + bias[gc];
                o.y = acc[mt][nt][rr * 2 + 1] + bias[gc + 1];
                *(float2*)&orow[gc] = o;
            }
        }
}

// ---------------- 3: LN over 512, fp32 + fp16 hi/lo outputs ----------------
__global__ void k_ln512(const float* __restrict__ lnq_g, const float* __restrict__ lnq_b,
                        const float* __restrict__ lnv_g, const float* __restrict__ lnv_b) {
    int sel = blockIdx.y;
    float* buf = sel ? g_V : g_Q;
    __half* oh = sel ? g_Vh : g_Qh;
    __half* ol = sel ? g_Vl : g_Ql;
    const float* lg = sel ? lnv_g : lnq_g;
    const float* lb = sel ? lnv_b : lnq_b;
    float scale = sel ? (1.0f / 196.0f) : 1.0f;
    int blk = blockIdx.x;
    int b = blk / NTOK, n = blk % NTOK;
    size_t ro = (size_t)(b * NP + n) * DIM;
    float* row = buf + ro;
    int tid = threadIdx.x;   // 128
    float4 v = ((float4*)row)[tid];
    float s = v.x + v.y + v.z + v.w;
    float s2 = v.x * v.x + v.y * v.y + v.z * v.z + v.w * v.w;
    block_reduce2(s, s2);
    float mu = s * (1.f / 512.f);
    float rs = rsqrtf(s2 * (1.f / 512.f) - mu * mu + LNEPS);
    float4 g4 = ((const float4*)lg)[tid], b4 = ((const float4*)lb)[tid];
    v.x = ((v.x - mu) * rs * g4.x + b4.x) * scale;
    v.y = ((v.y - mu) * rs * g4.y + b4.y) * scale;
    v.z = ((v.z - mu) * rs * g4.z + b4.z) * scale;
    v.w = ((v.w - mu) * rs * g4.w + b4.w) * scale;
    if (sel) ((float4*)row)[tid] = v;
    u64 lo, hi = split4h(v, lo);
    *(u64*)&oh[ro + tid * 4] = hi;
    *(u64*)&ol[ro + tid * 4] = lo;
}

// ---------------- 4: Gram GEMMs, ldmatrix ----------------
#define GR_AL (128*PASTR)
#define GR_BH (2*128*PASTR)
#define GR_BL (2*128*PASTR + 112*PASTR)
#define GR_SMEM ((2*128*PASTR + 2*112*PASTR)*2)   // 69120 B

template<int NTM>
__device__ __forceinline__ void gram_ks(float (&acc)[2][7][4],
    u32 aH, u32 aL, u32 bH, u32 bL)
{
#pragma unroll
    for (int ks = 0; ks < 4; ks++) {
        u32 ah[2][4], al[2][4];
        ldsm4(ah[0], aH + ks * 32);
        ldsm4(ah[1], aH + PMT + ks * 32);
        ldsm4(al[0], aL + ks * 32);
        ldsm4(al[1], aL + PMT + ks * 32);
#pragma unroll
        for (int pp = 0; pp < NTM / 2; pp++) {
            u32 bh4[4], bl4[4];
            ldsm4(bh4, bH + pp * PMT + ks * 32);
            ldsm4(bl4, bL + pp * PMT + ks * 32);
#pragma unroll
            for (int mt = 0; mt < 2; mt++) {
                mma16816h(acc[mt][2 * pp], ah[mt], bh4);
                mma16816h(acc[mt][2 * pp], al[mt], bh4);
                mma16816h(acc[mt][2 * pp], ah[mt], bl4);
                mma16816h(acc[mt][2 * pp + 1], ah[mt], bh4 + 2);
                mma16816h(acc[mt][2 * pp + 1], al[mt], bh4 + 2);
                mma16816h(acc[mt][2 * pp + 1], ah[mt], bl4 + 2);
            }
        }
        if (NTM & 1) {
            u32 bh2[2], bl2[2];
            ldsm2(bh2, bH + 3 * PMT + ks * 32);
            ldsm2(bl2, bL + 3 * PMT + ks * 32);
#pragma unroll
            for (int mt = 0; mt < 2; mt++) {
                mma16816h(acc[mt][6], ah[mt], bh2);
                mma16816h(acc[mt][6], al[mt], bh2);
                mma16816h(acc[mt][6], ah[mt], bl2);
            }
        }
    }
}

__global__ __launch_bounds__(256, 2) void k_gram_mma() {
    extern __shared__ __half sg[];
    u32 sb = smem_u32(sg);

    int zz = blockIdx.z;
    int b = zz >> 1, mode = zz & 1;
    const __half* Ah = (mode ? g_Qh : g_Vh) + (size_t)b * NP * DIM;
    const __half* Al = (mode ? g_Ql : g_Vl) + (size_t)b * NP * DIM;
    const __half* Bh = g_Vh + (size_t)b * NP * DIM;
    const __half* Bl = g_Vl + (size_t)b * NP * DIM;
    float* out = mode ? g_P : g_A;

    int m0 = blockIdx.x * 128, n0 = blockIdx.y * 112;
    int tid = threadIdx.x;
    int lane = tid & 31, wid = tid >> 5;
    int wm = wid & 3, wn = wid >> 2;
    int grp = lane >> 2, qid = lane & 3;
    bool full = !(blockIdx.y == 1 && wn == 1);

    u32 aHad = LDSM_A_ADDR(sb, wm * 32, PASTR, lane);
    u32 aLad = aHad + 2 * GR_AL;
    u32 bHad = LDSM_B_ADDR(sb + 2 * GR_BH, wn * 56, PASTR, lane);
    u32 bLad = bHad + 2 * (GR_BL - GR_BH);

    float acc[2][7][4];
#pragma unroll
    for (int mt = 0; mt < 2; mt++)
#pragma unroll
        for (int nt = 0; nt < 7; nt++)
#pragma unroll
            for (int j = 0; j < 4; j++) acc[mt][nt][j] = 0.f;

    for (int kc = 0; kc < 8; kc++) {
        int k0 = kc * 64;
        for (int i = tid; i < 1024; i += 256) {
            int r = i >> 3, q = i & 7;
            size_t go = (size_t)(m0 + r) * DIM + k0 + q * 8;
            u32 so = 2 * (r * PASTR + q * 8);
            cp16(sb + so, &Ah[go]);
            cp16(sb + 2 * GR_AL + so, &Al[go]);
        }
        for (int i = tid; i < 896; i += 256) {
            int r = i >> 3, q = i & 7;
            size_t go = (size_t)(n0 + r) * DIM + k0 + q * 8;
            u32 so = 2 * (r * PASTR + q * 8);
            cp16(sb + 2 * GR_BH + so, &Bh[go]);
            cp16(sb + 2 * GR_BL + so, &Bl[go]);
        }
        asm volatile("cp.async.commit_group;" ::: "memory");
        asm volatile("cp.async.wait_group 0;" ::: "memory");
        __syncthreads();
        if (full) gram_ks<7>(acc, aHad, aLad, bHad, bLad);
        else      gram_ks<4>(acc, aHad, aLad, bHad, bLad);
        __syncthreads();
    }
#pragma unroll
    for (int mt = 0; mt < 2; mt++)
#pragma unroll
        for (int rr = 0; rr < 2; rr++) {
            int gm = m0 + wm * 32 + mt * 16 + grp + rr * 8;
            if (gm >= NP) continue;
#pragma unroll
            for (int nt = 0; nt < 7; nt++) {
                if (!full && nt >= 4) continue;
                int gc = n0 + wn * 56 + nt * 8 + qid * 2;
                float a0 = acc[mt][nt][rr * 2 + 0];
                float a1 = acc[mt][nt][rr * 2 + 1];
                bool v0 = (gm < NTOK) && (gc < NTOK);
                bool v1 = (gm < NTOK) && (gc + 1 < NTOK);
                if (mode == 0) {
                    float q0 = v0 ? 2.f * a0 : 0.f;
                    float q1 = v1 ? 2.f * a1 : 0.f;
                    *(float2*)&out[(size_t)b * NPS + gm * NP + gc] = make_float2(q0, q1);
                    __half2 hh = __floats2half2_rn(q0, q1);
                    *(u32*)&g_Q1h[(size_t)b * NP * KP + gm * KP + gc] = *(u32*)&hh;
                } else {
                    float p0 = v0 ? (-2.f * a0 + (1.f / 196.f)) : 0.f;
                    float p1 = v1 ? (-2.f * a1 + (1.f / 196.f)) : 0.f;
                    *(float2*)&out[(size_t)b * NPS + gm * NP + gc] = make_float2(p0, p1);
                }
            }
        }
}

// =====================================================================
// 5: Neumann polynomial products, ldmatrix + pad-col skip.
// =====================================================================
__global__ __launch_bounds__(512, 1) void k_poly(
    const __half* __restrict__ Ag, const __half* __restrict__ Bg,
    const float* __restrict__ Q1f,
    __half* __restrict__ out1, __half* __restrict__ out2, int stage)
{
    extern __shared__ __half smh[];
    __half* sA = smh;
    __half* sB = smh + EOFF2;

    int tid = threadIdx.x;
    int lane = tid & 31, wid = tid >> 5;
    int wm = wid & 3, wn = wid >> 2;
    int grp = lane >> 2, qid = lane & 3;
    int rg = blockIdx.x, b = blockIdx.y;

    const __half* Ab = Ag + (size_t)b * NP * KP;
    const __half* Bb = Bg + (size_t)b * NP * KP;

    for (int idx = tid; idx < 224 * 28; idx += 512) {
        int row = idx / 28, c4 = idx - row * 28;
        *(float4*)&sB[row * ESTR + c4 * 8] = *(const float4*)&Bb[row * KP + c4 * 8];
    }
    for (int idx = tid; idx < 64 * 28; idx += 512) {
        int row = idx / 28, c4 = idx - row * 28;
        *(float4*)&sA[row * ASTR + c4 * 8] = *(const float4*)&Ab[(rg * 64 + row) * KP + c4 * 8];
    }
    __syncthreads();

    const int arow = wm * 16 + grp;
    const int cbase = wn * 56 + qid * 2;
    u32 aA = LDSM_A_ADDR(smem_u32(sA), wm * 16, ASTR, lane);
    u32 bA = LDSM_B_ADDR(smem_u32(sB), wn * 56, ESTR, lane);

    float acc[7][4];
#pragma unroll
    for (int nt = 0; nt < 7; nt++)
#pragma unroll
        for (int j = 0; j < 4; j++) acc[nt][j] = 0.f;

    if (wn < 3) mma_loop13<7>(acc, aA, bA);
    else        mma_loop13<4>(acc, aA, bA);

#pragma unroll
    for (int nt = 0; nt < 7; nt++) {
        if (wn == 3 && nt >= 4) continue;
        int cb = cbase + nt * 8;
#pragma unroll
        for (int rr = 0; rr < 2; rr++) {
            int grow = rg * 64 + arow + rr * 8;
            if (grow >= NP) continue;
            float a0 = acc[nt][rr * 2 + 0];
            float a1 = acc[nt][rr * 2 + 1];
            bool v0 = (grow < NTOK) && (cb < NTOK);
            bool v1 = (grow < NTOK) && (cb + 1 < NTOK);
            float q0 = v0 ? Q1f[(size_t)b * NPS + grow * NP + cb] : 0.f;
            float q1 = v1 ? Q1f[(size_t)b * NPS + grow * NP + cb + 1] : 0.f;
            size_t o = (size_t)b * NP * KP + grow * KP + cb;
            if (stage == 0) {
                __half2 sh2 = __floats2half2_rn(v0 ? a0 : 0.f, v1 ? a1 : 0.f);
                float m0v = v0 ? (((grow == cb) ? 1.f : 0.f) - q0 + a0) : 0.f;
                float m1v = v1 ? (((grow == cb + 1) ? 1.f : 0.f) - q1 + a1) : 0.f;
                __half2 mh2 = __floats2half2_rn(m0v, m1v);
                *(u32*)&out1[o] = *(u32*)&sh2;
                *(u32*)&out2[o] = *(u32*)&mh2;
            } else {
                __half2 e2 = __floats2half2_rn(v0 ? (a0 - q0) : 0.f, v1 ? (a1 - q1) : 0.f);
                *(u32*)&out1[o] = *(u32*)&e2;
            }
        }
    }
}

// =====================================================================
// 6: FUSED persistent ADMM, double-buffered A -> 1 barrier/iter.
// =====================================================================
__global__ __launch_bounds__(512, 1) void k_admm_fused(
    const float* __restrict__ Pg,
    const __half* __restrict__ ME,
    float* __restrict__ Zout)
{
    extern __shared__ __half smh[];
    __half* sE = smh + AD_EOFF;

    int tid = threadIdx.x;
    int lane = tid & 31, wid = tid >> 5;
    int wm = wid & 3, wn = wid >> 2;
    int grp = lane >> 2, qid = lane & 3;
    int rg = blockIdx.x, b = blockIdx.y;

    const float* Pr = Pg + (size_t)b * NPS + rg * 64 * NP;
    const __half* MEb = ME + (size_t)b * NP * KP;

    const int arow = wm * 16 + grp;
    const int cbase = wn * 56 + qid * 2;
    const int NTM = (wn == 3) ? 4 : 7;
    u32 aA0 = LDSM_A_ADDR(smem_u32(smh), wm * 16, ASTR, lane);
    u32 aA1 = aA0 + 64 * ASTR * 2;
    u32 bA = LDSM_B_ADDR(smem_u32(sE), wn * 56, ESTR, lane);

    for (int idx = tid; idx < 224 * 28; idx += 512) {
        int row = idx / 28, c4 = idx - row * 28;
        *(float4*)&sE[row * ESTR + c4 * 8] = *(const float4*)&MEb[row * KP + c4 * 8];
    }
    // zero BOTH A buffers once (skipped k-cols 200..207 + wn==3 regions stay 0)
    for (int idx = tid; idx < (128 * ASTR) / 2; idx += 512)
        ((u32*)smh)[idx] = 0u;

    float s[28], p[28];
#pragma unroll
    for (int nt = 0; nt < 7; nt++) {
        int cb = cbase + nt * 8;
#pragma unroll
        for (int rr = 0; rr < 2; rr++) {
            int i0 = nt * 4 + rr * 2;
            if (nt < NTM) {
                float2 p2 = *(const float2*)&Pr[(arow + rr * 8) * NP + cb];
                p[i0] = p2.x; p[i0 + 1] = p2.y;
            } else { p[i0] = 0.f; p[i0 + 1] = 0.f; }
            s[i0] = 0.f;  s[i0 + 1] = 0.f;
        }
    }
    __syncthreads();

    for (int iter = 0; iter < ITERS; iter++) {
        __half* sAb = smh + (iter & 1) * (64 * ASTR);
#pragma unroll
        for (int nt = 0; nt < 7; nt++) {
            if (nt >= NTM) continue;
            int cb = cbase + nt * 8;
#pragma unroll
            for (int rr = 0; rr < 2; rr++) {
                int i0 = nt * 4 + rr * 2;
                int r = arow + rr * 8;
                float z0 = fminf(fmaxf(s[i0], 0.f), 1.f);
                float z1 = fminf(fmaxf(s[i0 + 1], 0.f), 1.f);
                float r0 = 2.f * z0 - s[i0] - p[i0];
                float r1 = 2.f * z1 - s[i0 + 1] - p[i0 + 1];
                __half2 h2 = __floats2half2_rn(r0, r1);
                *(u32*)&sAb[r * ASTR + cb] = *(u32*)&h2;
            }
        }
        __syncthreads();   // the ONLY barrier per iteration

        float acc[7][4];
#pragma unroll
        for (int nt = 0; nt < 7; nt++)
#pragma unroll
            for (int j = 0; j < 4; j++) acc[nt][j] = 0.f;

        u32 aA = (iter & 1) ? aA1 : aA0;
        if (wn < 3) mma_loop13<7>(acc, aA, bA);
        else        mma_loop13<4>(acc, aA, bA);
        // no second barrier: next iter writes the OTHER A buffer; by the time
        // this buffer is written again (iter+2), the iter+1 barrier has
        // ordered all reads of it.

#pragma unroll
        for (int nt = 0; nt < 7; nt++) {
            if (nt >= NTM) continue;
#pragma unroll
            for (int j = 0; j < 4; j++) {
                int i = nt * 4 + j;
                float z = fminf(fmaxf(s[i], 0.f), 1.f);
                s[i] = acc[nt][j] + z - p[i];
            }
        }
    }

    float* Zo = Zout + (size_t)b * NPS;
#pragma unroll
    for (int nt = 0; nt < 7; nt++) {
        if (wn == 3 && nt >= 4) continue;
        int cb = cbase + nt * 8;
#pragma unroll
        for (int rr = 0; rr < 2; rr++) {
            int grow = rg * 64 + arow + rr * 8;
            if (grow < NP) {
                int i0 = nt * 4 + rr * 2;
                float z0 = fminf(fmaxf(s[i0], 0.f), 1.f);
                float z1 = fminf(fmaxf(s[i0 + 1], 0.f), 1.f);
                *(float2*)&Zo[grow * NP + cb] = make_float2(z0, z1);
            }
        }
    }
}

// ---------------- 7: pooled + head fused ----------------
__global__ void k_tail(const float* __restrict__ lg, const float* __restrict__ lb,
                       const float* __restrict__ W, const float* __restrict__ bias,
                       float* __restrict__ out) {
    int b = blockIdx.x;
    int tid = threadIdx.x;   // 256
    __shared__ float sI[196], sW[196];
    __shared__ float sx[DIM];
    const float* Zb = g_Z + (size_t)b * NPS;
    if (tid < 196) {
        float s = 0.f;
        const float* row = Zb + tid * NP;
        for (int m = 0; m < 196; m++) s += fabsf(row[m]);
        sI[tid] = 1.0f / (s + 1e-10f);
    }
    __syncthreads();
    if (tid < 196) {
        float w = 0.f;
        for (int n = 0; n < 196; n++) w += Zb[n * NP + tid] * sI[n];
        sW[tid] = w * (1.f / 196.f);
    }
    __syncthreads();
    const float* Vb = g_V + (size_t)b * NP * DIM;
    for (int d = tid; d < DIM; d += 256) {
        float acc = 0.f;
        for (int m = 0; m < 196; m++) acc += sW[m] * Vb[m * DIM + d];
        sx[d] = acc;
    }
    __syncthreads();
    float s = 0.f, s2 = 0.f;
    for (int d = tid; d < DIM; d += 256) {
        float v = sx[d];
        s += v; s2 += v * v;
    }
    block_reduce2(s, s2);
    float mu = s * (1.f / 512.f);
    float rs = rsqrtf(s2 * (1.f / 512.f) - mu * mu + LNEPS);
    __syncthreads();
    for (int d = tid; d < DIM; d += 256) sx[d] = (sx[d] - mu) * rs * lg[d] + lb[d];
    __syncthreads();
    float lgts[4];
    float mx = -1e30f;
#pragma unroll
    for (int t = 0; t < 4; t++) {
        int c = tid + t * 256;
        if (c < NCLS) {
            float acc = bias[c];
            for (int d = 0; d < DIM; d++) acc += sx[d] * W[d * NCLS + c];
            lgts[t] = acc;
            mx = fmaxf(mx, acc);
        } else lgts[t] = -1e30f;
    }
    __shared__ float red[32];
    for (int o = 16; o; o >>= 1) mx = fmaxf(mx, __shfl_xor_sync(0xffffffffu, mx, o));
    if ((tid & 31) == 0) red[tid >> 5] = mx;
    __syncthreads();
    float bm = red[0];
    for (int i = 1; i < 8; i++) bm = fmaxf(bm, red[i]);
    float es = 0.f;
#pragma unroll
    for (int t = 0; t < 4; t++) {
        int c = tid + t * 256;
        if (c < NCLS) { lgts[t] = expf(lgts[t] - bm); es += lgts[t]; }
    }
    float dummy = 0.f;
    block_reduce2(es, dummy);
#pragma unroll
    for (int t = 0; t < 4; t++) {
        int c = tid + t * 256;
        if (c < NCLS) out[b * NCLS + c] = lgts[t] / es;
    }
}

// ---------------- host ----------------
extern "C" void kernel_launch(void* const* d_in, const int* in_sizes, int n_in,
                              void* d_out, int out_size) {
    const float* img    = (const float*)d_in[0];
    const float* ln_pg  = (const float*)d_in[1];
    const float* ln_pb  = (const float*)d_in[2];
    const float* wq_w   = (const float*)d_in[3];
    const float* wq_b   = (const float*)d_in[4];
    const float* lnq_g  = (const float*)d_in[5];
    const float* lnq_b  = (const float*)d_in[6];
    const float* wv_w   = (const float*)d_in[7];
    const float* wv_b   = (const float*)d_in[8];
    const float* lnv_g  = (const float*)d_in[9];
    const float* lnv_b  = (const float*)d_in[10];
    const float* pos    = (const float*)d_in[11];
    const float* mlp_g  = (const float*)d_in[12];
    const float* mlp_b  = (const float*)d_in[13];
    const float* mlp_w  = (const float*)d_in[14];
    const float* mlp_bs = (const float*)d_in[15];
    float* out = (float*)d_out;

    float *pa, *pp, *pz;
    __half *pq1h, *psh, *pmh, *pme;
    cudaGetSymbolAddress((void**)&pa, g_A);
    cudaGetSymbolAddress((void**)&pp, g_P);
    cudaGetSymbolAddress((void**)&pz, g_Z);
    cudaGetSymbolAddress((void**)&pq1h, g_Q1h);
    cudaGetSymbolAddress((void**)&psh, g_Sh);
    cudaGetSymbolAddress((void**)&pmh, g_Mh);
    cudaGetSymbolAddress((void**)&pme, g_ME);

    cudaFuncSetAttribute(k_proj_mma, cudaFuncAttributeMaxDynamicSharedMemorySize, PJ_SMEM);
    cudaFuncSetAttribute(k_gram_mma, cudaFuncAttributeMaxDynamicSharedMemorySize, GR_SMEM);
    cudaFuncSetAttribute(k_poly, cudaFuncAttributeMaxDynamicSharedMemorySize, POLY_SMEM);
    cudaFuncSetAttribute(k_admm_fused, cudaFuncAttributeMaxDynamicSharedMemorySize, ADMM_SMEM);

    k_patch_wsplit<<<BATCH * NTOK + 768, 256>>>(img, ln_pg, ln_pb, pos, wq_w, wv_w);
    k_proj_mma<<<dim3(49, 4, 2), 256, PJ_SMEM>>>(wq_b, wv_b);
    k_ln512<<<dim3(BATCH * NTOK, 2), 128>>>(lnq_g, lnq_b, lnv_g, lnv_b);
    k_gram_mma<<<dim3(2, 2, BATCH * 2), 256, GR_SMEM>>>();
    k_poly<<<dim3(4, BATCH), 512, POLY_SMEM>>>(pq1h, pq1h, pa, psh, pmh, 0);
    k_poly<<<dim3(4, BATCH), 512, POLY_SMEM>>>(psh, pmh, pa, pme, nullptr, 1);
    k_admm_fused<<<dim3(4, BATCH), 512, ADMM_SMEM>>>(pp, pme, pz);
    k_tail<<<BATCH, 256>>>(mlp_g, mlp_b, mlp_w, mlp_bs, out);
}